// round 1
// baseline (speedup 1.0000x reference)
#include <cuda_runtime.h>
#include <math_constants.h>

// NNLoss: bidirectional 2-D nearest-neighbor loss.
// B=64, N=M=2048, F=4 (only first D=2 dims used), scalar fp32 output.
//
// Strategy: brute-force all-pairs argmin, both directions fused in one kernel.
// Database tile for one batch (2048 points) fits entirely in 32KB shared as
// float4 {tx, ty, ||t||^2, pad}. Inner loop per pair:
//   s = fma(-2px, tx, fma(-2py, ty, h))   (monotone in squared distance)
// Each thread owns 2 queries so the shared load amortizes across both.

namespace {
constexpr int Bc   = 64;
constexpr int Nc   = 2048;
constexpr int Fc   = 4;
constexpr int TPB  = 256;
constexpr int QPT  = 2;                       // queries per thread
constexpr int QPB  = TPB * QPT;               // 512 queries per block
constexpr int BLOCKS_PER_BATCH = Nc / QPB;    // 4
constexpr int BLOCKS_PER_DIR   = Bc * BLOCKS_PER_BATCH;  // 256
}

__global__ void nnloss_zero_kernel(float* out) {
    if (threadIdx.x == 0) out[0] = 0.0f;
}

__global__ __launch_bounds__(TPB)
void nnloss_kernel(const float* __restrict__ preds,
                   const float* __restrict__ targs,
                   const float* __restrict__ subcoef,
                   float* __restrict__ out)
{
    __shared__ float4 tile[Nc];        // {tx, ty, h=tx^2+ty^2, pad}
    __shared__ float  red[TPB / 32];

    int bid = blockIdx.x;
    const bool dir2 = (bid >= BLOCKS_PER_DIR);   // dir2: targs query preds
    if (dir2) bid -= BLOCKS_PER_DIR;
    const int b     = bid / BLOCKS_PER_BATCH;
    const int qbase = (bid % BLOCKS_PER_BATCH) * QPB;

    const float* qptr  = dir2 ? targs : preds;
    const float* dbptr = dir2 ? preds : targs;
    const float  c0    = dir2 ? 1.0f : subcoef[0];
    const float  c1    = dir2 ? 1.0f : subcoef[1];

    // Load the full database for this batch into shared (SoA-in-float4).
    const float4* dbv = reinterpret_cast<const float4*>(dbptr + (size_t)b * Nc * Fc);
    for (int j = threadIdx.x; j < Nc; j += TPB) {
        float4 t = dbv[j];
        tile[j] = make_float4(t.x, t.y, fmaf(t.x, t.x, t.y * t.y), 0.0f);
    }
    __syncthreads();

    // Two queries per thread.
    const float4* qv = reinterpret_cast<const float4*>(qptr + (size_t)b * Nc * Fc);
    const float4 q0 = qv[qbase + threadIdx.x];
    const float4 q1 = qv[qbase + TPB + threadIdx.x];
    const float nx0 = -2.0f * q0.x, ny0 = -2.0f * q0.y;
    const float nx1 = -2.0f * q1.x, ny1 = -2.0f * q1.y;

    float best0 = CUDART_INF_F, best1 = CUDART_INF_F;
    int   bj0 = 0, bj1 = 0;

#pragma unroll 8
    for (int j = 0; j < Nc; ++j) {
        float4 t = tile[j];
        float s0 = fmaf(nx0, t.x, fmaf(ny0, t.y, t.z));
        float s1 = fmaf(nx1, t.x, fmaf(ny1, t.y, t.z));
        // strict < keeps the FIRST index attaining the min (argmin semantics)
        if (s0 < best0) { best0 = s0; bj0 = j; }
        if (s1 < best1) { best1 = s1; bj1 = j; }
    }

    // Fetch winners from shared; accumulate weighted L1 contributions.
    const float4 t0 = tile[bj0];
    const float4 t1 = tile[bj1];
    float contrib = fabsf(q0.x - t0.x) * c0 + fabsf(q0.y - t0.y) * c1
                  + fabsf(q1.x - t1.x) * c0 + fabsf(q1.y - t1.y) * c1;

    // Block reduction, then one atomic per block.
#pragma unroll
    for (int o = 16; o > 0; o >>= 1)
        contrib += __shfl_down_sync(0xffffffffu, contrib, o);
    if ((threadIdx.x & 31) == 0) red[threadIdx.x >> 5] = contrib;
    __syncthreads();
    if (threadIdx.x < TPB / 32) {
        float v = red[threadIdx.x];
#pragma unroll
        for (int o = TPB / 64; o > 0; o >>= 1)
            v += __shfl_down_sync(0x000000ffu, v, o);
        if (threadIdx.x == 0) atomicAdd(out, v);
    }
}

extern "C" void kernel_launch(void* const* d_in, const int* in_sizes, int n_in,
                              void* d_out, int out_size)
{
    const float* preds   = (const float*)d_in[0];
    const float* targs   = (const float*)d_in[1];
    const float* subcoef = (const float*)d_in[2];
    float* out = (float*)d_out;

    nnloss_zero_kernel<<<1, 32>>>(out);
    nnloss_kernel<<<2 * BLOCKS_PER_DIR, TPB>>>(preds, targs, subcoef, out);
}

// round 2
// speedup vs baseline: 1.6578x; 1.6578x over previous
#include <cuda_runtime.h>
#include <math_constants.h>
#include <cstring>

// NNLoss: bidirectional 2-D NN loss, B=64, N=M=2048, D=2, scalar out.
// Brute-force all-pairs, but:
//  - packed fma.rn.f32x2: 2 candidates per FFMA2
//  - chunked argmin: FMNMX-only inner loop (1 alu op/pair), winning 64-wide
//    chunk recorded per query, exact neighbor recovered by a tiny rescan.

namespace {
constexpr int Bc   = 64;
constexpr int Nc   = 2048;
constexpr int Fc   = 4;
constexpr int TPB  = 128;
constexpr int QPT  = 4;                        // queries per thread
constexpr int QPB  = TPB * QPT;                // 512
constexpr int BLOCKS_PER_BATCH = Nc / QPB;     // 4
constexpr int BLOCKS_PER_DIR   = Bc * BLOCKS_PER_BATCH;  // 256
constexpr int CHUNK   = 64;                    // candidates per chunk
constexpr int NCHUNK  = Nc / CHUNK;            // 32
constexpr int PAIRS_PER_CHUNK = CHUNK / 2;     // 32
constexpr int PPAD    = PAIRS_PER_CHUNK + 1;   // 33: padded pair-stride per chunk
constexpr int NPAIR_PAD = NCHUNK * PPAD;       // 1056
}

__device__ __forceinline__ float2 fma2(float2 a, float2 b, float2 c) {
    unsigned long long au, bu, cu, du;
    memcpy(&au, &a, 8); memcpy(&bu, &b, 8); memcpy(&cu, &c, 8);
    asm("fma.rn.f32x2 %0, %1, %2, %3;" : "=l"(du) : "l"(au), "l"(bu), "l"(cu));
    float2 d; memcpy(&d, &du, 8);
    return d;
}

__global__ void nnloss_zero_kernel(float* out) {
    if (threadIdx.x == 0) out[0] = 0.0f;
}

__global__ __launch_bounds__(TPB)
void nnloss_kernel(const float* __restrict__ preds,
                   const float* __restrict__ targs,
                   const float* __restrict__ subcoef,
                   float* __restrict__ out)
{
    // pair p (candidates 2p, 2p+1) at padded slot p + p/32
    __shared__ float4 sxy[NPAIR_PAD];   // {x0, x1, y0, y1}
    __shared__ float2 shh[NPAIR_PAD];   // {h0, h1}, h = x^2 + y^2
    __shared__ float  red[TPB / 32];

    int bid = blockIdx.x;
    const bool dir2 = (bid >= BLOCKS_PER_DIR);   // dir2: targs query preds
    if (dir2) bid -= BLOCKS_PER_DIR;
    const int b     = bid / BLOCKS_PER_BATCH;
    const int qbase = (bid % BLOCKS_PER_BATCH) * QPB;

    const float* qptr  = dir2 ? targs : preds;
    const float* dbptr = dir2 ? preds : targs;
    const float  c0    = dir2 ? 1.0f : subcoef[0];
    const float  c1    = dir2 ? 1.0f : subcoef[1];

    // ---- load database tile into shared (pairwise, padded per chunk) ----
    const float4* dbv = reinterpret_cast<const float4*>(dbptr + (size_t)b * Nc * Fc);
    for (int p = threadIdx.x; p < Nc / 2; p += TPB) {
        float4 a = dbv[2 * p];
        float4 bb = dbv[2 * p + 1];
        int sp = p + (p >> 5);   // +1 pair pad per 32-pair chunk
        sxy[sp] = make_float4(a.x, bb.x, a.y, bb.y);
        shh[sp] = make_float2(fmaf(a.x, a.x, a.y * a.y),
                              fmaf(bb.x, bb.x, bb.y * bb.y));
    }
    __syncthreads();

    // ---- load queries, precompute broadcast-packed coefficients ----
    const float4* qv = reinterpret_cast<const float4*>(qptr + (size_t)b * Nc * Fc);
    float  qx[QPT], qy[QPT];
    float2 nx2[QPT], ny2[QPT];
#pragma unroll
    for (int k = 0; k < QPT; ++k) {
        float4 q = qv[qbase + threadIdx.x + k * TPB];
        qx[k] = q.x; qy[k] = q.y;
        float nx = -2.0f * q.x, ny = -2.0f * q.y;
        nx2[k] = make_float2(nx, nx);
        ny2[k] = make_float2(ny, ny);
    }

    float bestv[QPT];
    int   bestc[QPT];
#pragma unroll
    for (int k = 0; k < QPT; ++k) { bestv[k] = CUDART_INF_F; bestc[k] = 0; }

    // ---- main loop: FMNMX-only argmin over chunks ----
    for (int c = 0; c < NCHUNK; ++c) {
        const int base = c * PPAD;
        float aA[QPT], aB[QPT];
#pragma unroll
        for (int k = 0; k < QPT; ++k) { aA[k] = CUDART_INF_F; aB[k] = CUDART_INF_F; }

#pragma unroll 8
        for (int it = 0; it < PAIRS_PER_CHUNK; ++it) {
            float4 xy = sxy[base + it];
            float2 hh = shh[base + it];
            float2 tx = make_float2(xy.x, xy.y);
            float2 ty = make_float2(xy.z, xy.w);
#pragma unroll
            for (int k = 0; k < QPT; ++k) {
                float2 s = fma2(nx2[k], tx, fma2(ny2[k], ty, hh));
                aA[k] = fminf(aA[k], s.x);
                aB[k] = fminf(aB[k], s.y);
            }
        }
#pragma unroll
        for (int k = 0; k < QPT; ++k) {
            float cm = fminf(aA[k], aB[k]);
            // strict <  -> first chunk attaining the global min wins
            if (cm < bestv[k]) { bestv[k] = cm; bestc[k] = c; }
        }
    }

    // ---- rescan winning chunk per query (divergent, padded vs conflicts) ----
    float contrib = 0.0f;
#pragma unroll
    for (int k = 0; k < QPT; ++k) {
        const int cbase = bestc[k] * PPAD;
        const float nx = nx2[k].x, ny = ny2[k].x;
        float bv = CUDART_INF_F, bx = 0.0f, by = 0.0f;
        for (int j = 0; j < CHUNK; ++j) {
            int p = cbase + (j >> 1);
            int o = j & 1;
            const float* xp = reinterpret_cast<const float*>(&sxy[p]);
            float x = xp[o];
            float y = xp[2 + o];
            float h = reinterpret_cast<const float*>(&shh[p])[o];
            float s = fmaf(nx, x, fmaf(ny, y, h));
            if (s < bv) { bv = s; bx = x; by = y; }   // first-index tie-break
        }
        contrib += fabsf(qx[k] - bx) * c0 + fabsf(qy[k] - by) * c1;
    }

    // ---- block reduction + single atomic ----
#pragma unroll
    for (int o = 16; o > 0; o >>= 1)
        contrib += __shfl_down_sync(0xffffffffu, contrib, o);
    if ((threadIdx.x & 31) == 0) red[threadIdx.x >> 5] = contrib;
    __syncthreads();
    if (threadIdx.x < 32) {
        float v = (threadIdx.x < TPB / 32) ? red[threadIdx.x] : 0.0f;
#pragma unroll
        for (int o = 2; o > 0; o >>= 1)
            v += __shfl_down_sync(0x0000000fu, v, o);
        if (threadIdx.x == 0) atomicAdd(out, v);
    }
}

extern "C" void kernel_launch(void* const* d_in, const int* in_sizes, int n_in,
                              void* d_out, int out_size)
{
    const float* preds   = (const float*)d_in[0];
    const float* targs   = (const float*)d_in[1];
    const float* subcoef = (const float*)d_in[2];
    float* out = (float*)d_out;

    nnloss_zero_kernel<<<1, 32>>>(out);
    nnloss_kernel<<<2 * BLOCKS_PER_DIR, TPB>>>(preds, targs, subcoef, out);
}

// round 3
// speedup vs baseline: 1.7423x; 1.0510x over previous
#include <cuda_runtime.h>
#include <math_constants.h>
#include <cstring>

// NNLoss: bidirectional 2-D NN loss, B=64, N=M=2048, D=2, scalar out.
// Pass 1: brute-force partial argmin, candidate set split in two halves per
//         block for occupancy. FFMA2 packed distances, FMNMX-only inner loop,
//         chunk-granular argmin + rescan.
// Pass 2: combine halves (first-index tie-break), weighted L1, reduce.

namespace {
constexpr int Bc   = 64;
constexpr int Nc   = 2048;
constexpr int Fc   = 4;
constexpr int TPB  = 256;
constexpr int QPT  = 2;                         // queries per thread
constexpr int QPB  = TPB * QPT;                 // 512
constexpr int QBLK = Nc / QPB;                  // 4 query-blocks per batch
constexpr int NHALF = 2;                        // candidate halves
constexpr int CANDS = Nc / NHALF;               // 1024 per half
constexpr int CHUNK = 64;                       // candidates per chunk
constexpr int NCHUNK = CANDS / CHUNK;           // 16
constexpr int GPC   = CHUNK / 4;                // 16 groups (of 4 cands) per chunk
constexpr int GPAD  = GPC + 1;                  // 17: padded group stride
constexpr int NG    = NCHUNK * GPAD;            // 272 float4 slots
constexpr int NQ_TOTAL = 2 * Bc * Nc;           // 262144 (dir, b, q)
}

__device__ float4 g_scratch[NQ_TOTAL * NHALF];  // {bestval, bx, by, 0}

__device__ __forceinline__ float2 fma2(float2 a, float2 b, float2 c) {
    unsigned long long au, bu, cu, du;
    memcpy(&au, &a, 8); memcpy(&bu, &b, 8); memcpy(&cu, &c, 8);
    asm("fma.rn.f32x2 %0, %1, %2, %3;" : "=l"(du) : "l"(au), "l"(bu), "l"(cu));
    float2 d; memcpy(&d, &du, 8);
    return d;
}

__global__ void nnloss_zero_kernel(float* out) {
    if (threadIdx.x == 0) out[0] = 0.0f;
}

// ---------------- Pass 1: partial argmin per (query, half) ----------------
__global__ __launch_bounds__(TPB)
void nnloss_partial_kernel(const float* __restrict__ preds,
                           const float* __restrict__ targs)
{
    __shared__ float4 sx[NG];   // x of cands 4g..4g+3
    __shared__ float4 sy[NG];
    __shared__ float4 sh[NG];   // h = x^2 + y^2

    // bid = (((dir*Bc + b)*QBLK + qblk)*NHALF + half)
    int bid = blockIdx.x;
    const int half = bid & (NHALF - 1);  bid >>= 1;
    const int qblk = bid & (QBLK - 1);   bid >>= 2;
    const int b    = bid & (Bc - 1);     bid >>= 6;
    const int dir  = bid;                // 0: preds->targs, 1: targs->preds

    const float* qptr  = dir ? targs : preds;
    const float* dbptr = dir ? preds : targs;

    // ---- load this half's candidates into shared ----
    const float4* dbv = reinterpret_cast<const float4*>(dbptr + (size_t)b * Nc * Fc)
                      + half * CANDS;
    {
        int g = threadIdx.x;             // one group of 4 candidates per thread
        float4 a0 = dbv[4 * g + 0];
        float4 a1 = dbv[4 * g + 1];
        float4 a2 = dbv[4 * g + 2];
        float4 a3 = dbv[4 * g + 3];
        int sg = g + (g >> 4);           // +1 slot pad per 16-group chunk
        sx[sg] = make_float4(a0.x, a1.x, a2.x, a3.x);
        sy[sg] = make_float4(a0.y, a1.y, a2.y, a3.y);
        sh[sg] = make_float4(fmaf(a0.x, a0.x, a0.y * a0.y),
                             fmaf(a1.x, a1.x, a1.y * a1.y),
                             fmaf(a2.x, a2.x, a2.y * a2.y),
                             fmaf(a3.x, a3.x, a3.y * a3.y));
    }
    __syncthreads();

    // ---- queries ----
    const float4* qv = reinterpret_cast<const float4*>(qptr + (size_t)b * Nc * Fc);
    int qidx[QPT];
    float2 nx2[QPT], ny2[QPT];
#pragma unroll
    for (int k = 0; k < QPT; ++k) {
        qidx[k] = qblk * QPB + threadIdx.x + k * TPB;
        float4 q = qv[qidx[k]];
        float nx = -2.0f * q.x, ny = -2.0f * q.y;
        nx2[k] = make_float2(nx, nx);
        ny2[k] = make_float2(ny, ny);
    }

    float bestv[QPT];
    int   bestc[QPT];
#pragma unroll
    for (int k = 0; k < QPT; ++k) { bestv[k] = CUDART_INF_F; bestc[k] = 0; }

    // ---- main loop over chunks ----
    for (int c = 0; c < NCHUNK; ++c) {
        const int base = c * GPAD;
        float aA[QPT], aB[QPT];
#pragma unroll
        for (int k = 0; k < QPT; ++k) { aA[k] = CUDART_INF_F; aB[k] = CUDART_INF_F; }

#pragma unroll 8
        for (int it = 0; it < GPC; ++it) {
            float4 x4 = sx[base + it];
            float4 y4 = sy[base + it];
            float4 h4 = sh[base + it];
            float2 tx01 = make_float2(x4.x, x4.y), tx23 = make_float2(x4.z, x4.w);
            float2 ty01 = make_float2(y4.x, y4.y), ty23 = make_float2(y4.z, y4.w);
            float2 hh01 = make_float2(h4.x, h4.y), hh23 = make_float2(h4.z, h4.w);
#pragma unroll
            for (int k = 0; k < QPT; ++k) {
                float2 s01 = fma2(nx2[k], tx01, fma2(ny2[k], ty01, hh01));
                float2 s23 = fma2(nx2[k], tx23, fma2(ny2[k], ty23, hh23));
                aA[k] = fminf(aA[k], s01.x);
                aB[k] = fminf(aB[k], s01.y);
                aA[k] = fminf(aA[k], s23.x);
                aB[k] = fminf(aB[k], s23.y);
            }
        }
#pragma unroll
        for (int k = 0; k < QPT; ++k) {
            float cm = fminf(aA[k], aB[k]);
            if (cm < bestv[k]) { bestv[k] = cm; bestc[k] = c; }  // first chunk wins ties
        }
    }

    // ---- rescan winning chunk, write partial result ----
#pragma unroll
    for (int k = 0; k < QPT; ++k) {
        const int cbase = bestc[k] * GPAD;
        const float nx = nx2[k].x, ny = ny2[k].x;
        float bv = CUDART_INF_F, bx = 0.0f, by = 0.0f;
        for (int j = 0; j < CHUNK; ++j) {
            int g = cbase + (j >> 2);
            int o = j & 3;
            float x = reinterpret_cast<const float*>(&sx[g])[o];
            float y = reinterpret_cast<const float*>(&sy[g])[o];
            float h = reinterpret_cast<const float*>(&sh[g])[o];
            float s = fmaf(nx, x, fmaf(ny, y, h));
            if (s < bv) { bv = s; bx = x; by = y; }   // first-index tie-break
        }
        size_t sidx = ((size_t)((dir * Bc + b) * Nc + qidx[k])) * NHALF + half;
        g_scratch[sidx] = make_float4(bv, bx, by, 0.0f);
    }
}

// ---------------- Pass 2: combine halves, weighted L1, reduce ----------------
__global__ __launch_bounds__(256)
void nnloss_combine_kernel(const float* __restrict__ preds,
                           const float* __restrict__ targs,
                           const float* __restrict__ subcoef,
                           float* __restrict__ out)
{
    __shared__ float red[8];
    int idx = blockIdx.x * 256 + threadIdx.x;     // (dir, b, q)
    const int dir = idx >> 17;
    const int rem = idx & ((Bc * Nc) - 1);
    const int b   = rem >> 11;
    const int q   = rem & (Nc - 1);

    float4 s0 = g_scratch[(size_t)idx * NHALF + 0];
    float4 s1 = g_scratch[(size_t)idx * NHALF + 1];
    float4 w  = (s1.x < s0.x) ? s1 : s0;          // tie -> half 0 (lower index)

    const float* qptr = dir ? targs : preds;
    float4 qq = reinterpret_cast<const float4*>(qptr + (size_t)b * Nc * Fc)[q];
    const float c0 = dir ? 1.0f : subcoef[0];
    const float c1 = dir ? 1.0f : subcoef[1];

    float contrib = fabsf(qq.x - w.y) * c0 + fabsf(qq.y - w.z) * c1;

#pragma unroll
    for (int o = 16; o > 0; o >>= 1)
        contrib += __shfl_down_sync(0xffffffffu, contrib, o);
    if ((threadIdx.x & 31) == 0) red[threadIdx.x >> 5] = contrib;
    __syncthreads();
    if (threadIdx.x < 32) {
        float v = (threadIdx.x < 8) ? red[threadIdx.x] : 0.0f;
#pragma unroll
        for (int o = 4; o > 0; o >>= 1)
            v += __shfl_down_sync(0x000000ffu, v, o);
        if (threadIdx.x == 0) atomicAdd(out, v);
    }
}

extern "C" void kernel_launch(void* const* d_in, const int* in_sizes, int n_in,
                              void* d_out, int out_size)
{
    const float* preds   = (const float*)d_in[0];
    const float* targs   = (const float*)d_in[1];
    const float* subcoef = (const float*)d_in[2];
    float* out = (float*)d_out;

    nnloss_zero_kernel<<<1, 32>>>(out);
    const int grid1 = 2 * Bc * QBLK * NHALF;      // 1024
    nnloss_partial_kernel<<<grid1, TPB>>>(preds, targs);
    nnloss_combine_kernel<<<NQ_TOTAL / 256, 256>>>(preds, targs, subcoef, out);
}

// round 4
// speedup vs baseline: 2.2610x; 1.2977x over previous
#include <cuda_runtime.h>
#include <math_constants.h>

// NNLoss: bidirectional 2-D NN loss via uniform-grid spatial binning.
// zero -> count -> scan -> scatter -> ring-search query (+inline reduce).

namespace {
constexpr int   Bc   = 64;
constexpr int   Nc   = 2048;
constexpr int   NSB  = 2 * Bc;            // (set, batch) segments = 128
constexpr int   G    = 64;
constexpr int   G2   = G * G;             // 4096 cells
constexpr int   SST  = G2 + 8;            // starts stride (padded)
constexpr float EXT  = 6.0f;
constexpr float CELL = 2.0f * EXT / G;    // 0.1875
constexpr float INVC = (float)G / (2.0f * EXT);
constexpr int   TPB  = 256;
constexpr int   NPTS = NSB * Nc;          // 262144
constexpr int   QCH  = Nc / TPB;          // 8 query chunks per (dir,b)
}

__device__ unsigned int   g_cnt[NSB * G2];      // counts, then scatter cursors
__device__ unsigned short g_start[NSB * SST];   // exclusive cell starts (+total)
__device__ float4         g_sorted[NSB * Nc];   // cell-sorted {x, y, x^2+y^2, 0}

__device__ __forceinline__ int cell_of(float v) {
    int c = __float2int_rd((v + EXT) * INVC);
    return min(G - 1, max(0, c));
}

__global__ void zero_kernel(float* out) {
    int i = blockIdx.x * TPB + threadIdx.x;      // 524288 counters
    g_cnt[i] = 0u;
    if (i == 0) out[0] = 0.0f;
}

__global__ void count_kernel(const float* __restrict__ preds,
                             const float* __restrict__ targs) {
    int idx = blockIdx.x * TPB + threadIdx.x;    // 262144
    int set = idx >> 17;
    int rem = idx & (Bc * Nc - 1);               // b*2048 + i
    const float4* src = reinterpret_cast<const float4*>(set ? targs : preds);
    float4 p = src[rem];
    int sb = (set << 6) + (rem >> 11);
    atomicAdd(&g_cnt[sb * G2 + cell_of(p.y) * G + cell_of(p.x)], 1u);
}

__global__ __launch_bounds__(TPB) void scan_kernel() {
    const int sb = blockIdx.x;                   // 128 segments
    unsigned int*   cnt = g_cnt   + sb * G2;
    unsigned short* st  = g_start + sb * SST;
    __shared__ unsigned int part[TPB];

    unsigned int v[16], sum = 0;
    const int base = threadIdx.x * 16;
#pragma unroll
    for (int i = 0; i < 16; ++i) { v[i] = cnt[base + i]; sum += v[i]; }
    part[threadIdx.x] = sum;
    __syncthreads();
    for (int off = 1; off < TPB; off <<= 1) {
        unsigned int a = (threadIdx.x >= off) ? part[threadIdx.x - off] : 0u;
        __syncthreads();
        if (threadIdx.x >= off) part[threadIdx.x] += a;
        __syncthreads();
    }
    unsigned int run = threadIdx.x ? part[threadIdx.x - 1] : 0u;
#pragma unroll
    for (int i = 0; i < 16; ++i) {
        cnt[base + i] = run;                     // scatter cursor
        st[base + i]  = (unsigned short)run;
        run += v[i];
    }
    if (threadIdx.x == TPB - 1) st[G2] = (unsigned short)run;   // = 2048
}

__global__ void scatter_kernel(const float* __restrict__ preds,
                               const float* __restrict__ targs) {
    int idx = blockIdx.x * TPB + threadIdx.x;
    int set = idx >> 17;
    int rem = idx & (Bc * Nc - 1);
    const float4* src = reinterpret_cast<const float4*>(set ? targs : preds);
    float4 p = src[rem];
    int sb = (set << 6) + (rem >> 11);
    unsigned int pos = atomicAdd(&g_cnt[sb * G2 + cell_of(p.y) * G + cell_of(p.x)], 1u);
    g_sorted[sb * Nc + pos] = make_float4(p.x, p.y, fmaf(p.x, p.x, p.y * p.y), 0.0f);
}

__global__ __launch_bounds__(TPB)
void query_kernel(const float* __restrict__ subcoef, float* __restrict__ out) {
    __shared__ float4 tile[Nc];                  // db points (cell-sorted)
    __shared__ unsigned short sst[G2 + 1];       // db cell starts
    __shared__ float red[TPB / 32];

    int bid = blockIdx.x;
    const int chunk = bid & (QCH - 1);  bid >>= 3;
    const int b     = bid & (Bc - 1);   bid >>= 6;
    const int dir   = bid;                       // 0: preds->targs, 1: targs->preds
    const int qsb = dir * Bc + b;                // query set = dir (set0 = preds)
    const int dsb = (1 - dir) * Bc + b;          // db set

    for (int t = threadIdx.x; t < Nc; t += TPB)  tile[t] = g_sorted[dsb * Nc + t];
    for (int t = threadIdx.x; t <= G2; t += TPB) sst[t]  = g_start[dsb * SST + t];
    __syncthreads();

    // query = own set's sorted points (loss is order-invariant; spatial sort
    // makes warp lanes cell-coherent)
    float4 q = g_sorted[qsb * Nc + chunk * TPB + threadIdx.x];
    const float nx = -2.0f * q.x, ny = -2.0f * q.y, qh = q.z;
    const int cx = cell_of(q.x), cy = cell_of(q.y);

    float best = CUDART_INF_F;                   // s = d^2 - |q|^2 (monotone)
    int   bj   = 0;

    for (int k = 0; k < G; ++k) {
        if (k >= 1) {
            // any point in an unscanned cell (Chebyshev >= k) has d >= (k-1)*CELL
            float bd = (float)(k - 1) * CELL;
            if (best <= fmaf(bd, bd, -qh)) break;
        }
        const int xa = max(cx - k, 0), xb = min(cx + k, G - 1);
        const int ya = max(cy - k, 0), yb = min(cy + k, G - 1);
        for (int y = ya; y <= yb; ++y) {
            if (k == 0 || y == cy - k || y == cy + k) {
                // full ring row: contiguous span of cells xa..xb
                int j  = sst[y * G + xa];
                int je = sst[y * G + xb + 1];
                for (; j < je; ++j) {
                    float4 t = tile[j];
                    float s = fmaf(nx, t.x, fmaf(ny, t.y, t.z));
                    if (s < best) { best = s; bj = j; }
                }
            } else {
                if (cx - k >= 0) {
                    int cc = y * G + cx - k;
                    int j = sst[cc], je = sst[cc + 1];
                    for (; j < je; ++j) {
                        float4 t = tile[j];
                        float s = fmaf(nx, t.x, fmaf(ny, t.y, t.z));
                        if (s < best) { best = s; bj = j; }
                    }
                }
                if (cx + k < G) {
                    int cc = y * G + cx + k;
                    int j = sst[cc], je = sst[cc + 1];
                    for (; j < je; ++j) {
                        float4 t = tile[j];
                        float s = fmaf(nx, t.x, fmaf(ny, t.y, t.z));
                        if (s < best) { best = s; bj = j; }
                    }
                }
            }
        }
    }

    float4 w = tile[bj];
    const float cA = dir ? 1.0f : subcoef[0];
    const float cB = dir ? 1.0f : subcoef[1];
    float contrib = fabsf(q.x - w.x) * cA + fabsf(q.y - w.y) * cB;

#pragma unroll
    for (int o = 16; o > 0; o >>= 1)
        contrib += __shfl_down_sync(0xffffffffu, contrib, o);
    if ((threadIdx.x & 31) == 0) red[threadIdx.x >> 5] = contrib;
    __syncthreads();
    if (threadIdx.x < 32) {
        float v = (threadIdx.x < TPB / 32) ? red[threadIdx.x] : 0.0f;
#pragma unroll
        for (int o = 4; o > 0; o >>= 1)
            v += __shfl_down_sync(0x000000ffu, v, o);
        if (threadIdx.x == 0) atomicAdd(out, v);
    }
}

extern "C" void kernel_launch(void* const* d_in, const int* in_sizes, int n_in,
                              void* d_out, int out_size)
{
    const float* preds   = (const float*)d_in[0];
    const float* targs   = (const float*)d_in[1];
    const float* subcoef = (const float*)d_in[2];
    float* out = (float*)d_out;

    zero_kernel   <<<(NSB * G2) / TPB, TPB>>>(out);       // 2048 blocks
    count_kernel  <<<NPTS / TPB, TPB>>>(preds, targs);    // 1024
    scan_kernel   <<<NSB, TPB>>>();                       // 128
    scatter_kernel<<<NPTS / TPB, TPB>>>(preds, targs);    // 1024
    query_kernel  <<<2 * Bc * QCH, TPB>>>(subcoef, out);  // 1024
}

// round 5
// speedup vs baseline: 2.4971x; 1.1045x over previous
#include <cuda_runtime.h>
#include <math_constants.h>

// NNLoss: bidirectional 2-D NN loss via uniform-grid spatial binning.
// Kernel 1: per-(set,batch) block-local bin (count+scan+scatter in shared).
// Kernel 2: ring-search query (3x3 box fast path + expanding rings) + reduce.

namespace {
constexpr int   Bc   = 64;
constexpr int   Nc   = 2048;
constexpr int   NSB  = 2 * Bc;            // (set, batch) segments = 128
constexpr int   G    = 64;
constexpr int   G2   = G * G;             // 4096 cells
constexpr int   SST  = G2 + 8;            // starts stride (padded)
constexpr float EXT  = 6.0f;
constexpr float CELL = 2.0f * EXT / G;    // 0.1875
constexpr float INVC = (float)G / (2.0f * EXT);
constexpr int   TPB  = 256;
constexpr int   QPT  = 2;                 // queries per thread
constexpr int   QPB  = TPB * QPT;         // 512
constexpr int   QCH  = Nc / QPB;          // 4 query chunks per (dir,b)
}

__device__ unsigned short g_start[NSB * SST];   // exclusive cell starts (+total)
__device__ float4         g_sorted[NSB * Nc];   // cell-sorted {x, y, x^2+y^2, 0}

__device__ __forceinline__ int cell_of(float v) {
    int c = __float2int_rd((v + EXT) * INVC);
    return min(G - 1, max(0, c));
}

// ---------------- Kernel 1: block-local binning ----------------
__global__ __launch_bounds__(TPB)
void bin_kernel(const float* __restrict__ preds,
                const float* __restrict__ targs,
                float* __restrict__ out)
{
    __shared__ unsigned int scnt[G2];      // counts -> starts -> scatter cursors
    __shared__ float4 pts[Nc];
    __shared__ unsigned int part[TPB];

    const int sb  = blockIdx.x;            // set*64 + b
    const int set = sb >> 6;
    const int b   = sb & (Bc - 1);
    if (sb == 0 && threadIdx.x == 0) out[0] = 0.0f;

    // load points + zero counters
    const float4* src = reinterpret_cast<const float4*>(set ? targs : preds)
                      + (size_t)b * Nc;
#pragma unroll
    for (int i = 0; i < Nc / TPB; ++i)
        pts[threadIdx.x + i * TPB] = src[threadIdx.x + i * TPB];
#pragma unroll
    for (int i = 0; i < G2 / TPB; ++i)
        scnt[threadIdx.x + i * TPB] = 0u;
    __syncthreads();

    // count (shared atomics, spread addresses)
#pragma unroll
    for (int i = 0; i < Nc / TPB; ++i) {
        float4 p = pts[threadIdx.x + i * TPB];
        atomicAdd(&scnt[cell_of(p.y) * G + cell_of(p.x)], 1u);
    }
    __syncthreads();

    // block exclusive scan of 4096 counters (16 per thread + log-scan)
    unsigned int v[16], sum = 0;
    const int base = threadIdx.x * 16;
#pragma unroll
    for (int i = 0; i < 16; ++i) { v[i] = scnt[base + i]; sum += v[i]; }
    part[threadIdx.x] = sum;
    __syncthreads();
    for (int off = 1; off < TPB; off <<= 1) {
        unsigned int a = (threadIdx.x >= off) ? part[threadIdx.x - off] : 0u;
        __syncthreads();
        if (threadIdx.x >= off) part[threadIdx.x] += a;
        __syncthreads();
    }
    unsigned int run = threadIdx.x ? part[threadIdx.x - 1] : 0u;
    unsigned short* st = g_start + sb * SST;
#pragma unroll
    for (int i = 0; i < 16; ++i) {
        scnt[base + i] = run;                       // scatter cursor
        st[base + i]   = (unsigned short)run;
        run += v[i];
    }
    if (threadIdx.x == TPB - 1) st[G2] = (unsigned short)run;   // 2048
    __syncthreads();

    // scatter (shared cursor atomics, L2-local stores)
    float4* dst = g_sorted + (size_t)sb * Nc;
#pragma unroll
    for (int i = 0; i < Nc / TPB; ++i) {
        float4 p = pts[threadIdx.x + i * TPB];
        unsigned int pos = atomicAdd(&scnt[cell_of(p.y) * G + cell_of(p.x)], 1u);
        dst[pos] = make_float4(p.x, p.y, fmaf(p.x, p.x, p.y * p.y), 0.0f);
    }
}

// ---------------- Kernel 2: ring-search query ----------------
__global__ __launch_bounds__(TPB)
void query_kernel(const float* __restrict__ subcoef, float* __restrict__ out)
{
    __shared__ float4 tile[Nc];                  // db points (cell-sorted)
    __shared__ unsigned short sst[G2 + 1];       // db cell starts
    __shared__ float red[TPB / 32];

    int bid = blockIdx.x;
    const int chunk = bid & (QCH - 1);  bid >>= 2;
    const int b     = bid & (Bc - 1);   bid >>= 6;
    const int dir   = bid;                       // 0: preds->targs, 1: targs->preds
    const int qsb = dir * Bc + b;                // query set (set0 = preds)
    const int dsb = (1 - dir) * Bc + b;          // db set

    for (int t = threadIdx.x; t < Nc; t += TPB)  tile[t] = g_sorted[(size_t)dsb * Nc + t];
    for (int t = threadIdx.x; t <= G2; t += TPB) sst[t]  = g_start[dsb * SST + t];
    __syncthreads();

    const float cA = dir ? 1.0f : subcoef[0];
    const float cB = dir ? 1.0f : subcoef[1];
    float contrib = 0.0f;

#pragma unroll
    for (int kq = 0; kq < QPT; ++kq) {
        // queries = own set's sorted points (order-invariant loss; spatial
        // sort makes warp lanes cell-coherent)
        float4 q = g_sorted[(size_t)qsb * Nc + chunk * QPB + threadIdx.x + kq * TPB];
        const float nx = -2.0f * q.x, ny = -2.0f * q.y, qh = q.z;
        const int cx = cell_of(q.x), cy = cell_of(q.y);

        float best = CUDART_INF_F;               // s = d^2 - |q|^2 (monotone)
        int   bj   = 0;

        // fast path: unconditional 3x3 box (rings k=0,1), 3 contiguous rows
        {
            const int xa = max(cx - 1, 0), xb = min(cx + 1, G - 1);
            const int ya = max(cy - 1, 0), yb = min(cy + 1, G - 1);
            for (int y = ya; y <= yb; ++y) {
                int j  = sst[y * G + xa];
                int je = sst[y * G + xb + 1];
                for (; j < je; ++j) {
                    float4 t = tile[j];
                    float s = fmaf(nx, t.x, fmaf(ny, t.y, t.z));
                    if (s < best) { best = s; bj = j; }
                }
            }
        }

        // expansion: ring k; unscanned cells (Chebyshev >= k) have d >= (k-1)*CELL
        for (int k = 2; k < G; ++k) {
            float bd = (float)(k - 1) * CELL;
            if (best <= fmaf(bd, bd, -qh)) break;
            const int xa = max(cx - k, 0), xb = min(cx + k, G - 1);
            const int ya = max(cy - k, 0), yb = min(cy + k, G - 1);
            for (int y = ya; y <= yb; ++y) {
                if (y == cy - k || y == cy + k) {
                    int j  = sst[y * G + xa];
                    int je = sst[y * G + xb + 1];
                    for (; j < je; ++j) {
                        float4 t = tile[j];
                        float s = fmaf(nx, t.x, fmaf(ny, t.y, t.z));
                        if (s < best) { best = s; bj = j; }
                    }
                } else {
                    if (cx - k >= 0) {
                        int cc = y * G + cx - k;
                        int j = sst[cc], je = sst[cc + 1];
                        for (; j < je; ++j) {
                            float4 t = tile[j];
                            float s = fmaf(nx, t.x, fmaf(ny, t.y, t.z));
                            if (s < best) { best = s; bj = j; }
                        }
                    }
                    if (cx + k < G) {
                        int cc = y * G + cx + k;
                        int j = sst[cc], je = sst[cc + 1];
                        for (; j < je; ++j) {
                            float4 t = tile[j];
                            float s = fmaf(nx, t.x, fmaf(ny, t.y, t.z));
                            if (s < best) { best = s; bj = j; }
                        }
                    }
                }
            }
        }

        float4 w = tile[bj];
        contrib += fabsf(q.x - w.x) * cA + fabsf(q.y - w.y) * cB;
    }

#pragma unroll
    for (int o = 16; o > 0; o >>= 1)
        contrib += __shfl_down_sync(0xffffffffu, contrib, o);
    if ((threadIdx.x & 31) == 0) red[threadIdx.x >> 5] = contrib;
    __syncthreads();
    if (threadIdx.x < 32) {
        float v = (threadIdx.x < TPB / 32) ? red[threadIdx.x] : 0.0f;
#pragma unroll
        for (int o = 4; o > 0; o >>= 1)
            v += __shfl_down_sync(0x000000ffu, v, o);
        if (threadIdx.x == 0) atomicAdd(out, v);
    }
}

extern "C" void kernel_launch(void* const* d_in, const int* in_sizes, int n_in,
                              void* d_out, int out_size)
{
    const float* preds   = (const float*)d_in[0];
    const float* targs   = (const float*)d_in[1];
    const float* subcoef = (const float*)d_in[2];
    float* out = (float*)d_out;

    bin_kernel  <<<NSB, TPB>>>(preds, targs, out);          // 128 blocks
    query_kernel<<<2 * Bc * QCH, TPB>>>(subcoef, out);      // 512 blocks
}

// round 6
// speedup vs baseline: 2.6057x; 1.0435x over previous
#include <cuda_runtime.h>
#include <math_constants.h>

// NNLoss: bidirectional 2-D NN loss via uniform-grid spatial binning.
// Kernel 1: per-(set,batch) block-local bin (count+scan+scatter in shared).
// Kernel 2: ring-search query, float2 tile, unroll-2 spans, QPT=1.

namespace {
constexpr int   Bc   = 64;
constexpr int   Nc   = 2048;
constexpr int   NSB  = 2 * Bc;            // (set, batch) segments = 128
constexpr int   G    = 64;
constexpr int   G2   = G * G;             // 4096 cells
constexpr int   SST  = G2 + 8;            // starts stride (padded)
constexpr float EXT  = 6.0f;
constexpr float CELL = 2.0f * EXT / G;    // 0.1875
constexpr float INVC = (float)G / (2.0f * EXT);
constexpr int   TPB  = 256;
constexpr int   QCH  = Nc / TPB;          // 8 query chunks per (dir,b)
}

__device__ unsigned short g_start[NSB * SST];   // exclusive cell starts (+total)
__device__ float2         g_sorted[NSB * Nc];   // cell-sorted {x, y}

__device__ __forceinline__ int cell_of(float v) {
    int c = __float2int_rd((v + EXT) * INVC);
    return min(G - 1, max(0, c));
}

// ---------------- Kernel 1: block-local binning ----------------
__global__ __launch_bounds__(TPB)
void bin_kernel(const float* __restrict__ preds,
                const float* __restrict__ targs,
                float* __restrict__ out)
{
    __shared__ unsigned int scnt[G2];      // counts -> scatter cursors
    __shared__ float2 pts[Nc];
    __shared__ unsigned int part[TPB];

    const int sb  = blockIdx.x;            // set*64 + b
    const int set = sb >> 6;
    const int b   = sb & (Bc - 1);
    if (sb == 0 && threadIdx.x == 0) out[0] = 0.0f;

    const float4* src = reinterpret_cast<const float4*>(set ? targs : preds)
                      + (size_t)b * Nc;
#pragma unroll
    for (int i = 0; i < Nc / TPB; ++i) {
        float4 p = src[threadIdx.x + i * TPB];
        pts[threadIdx.x + i * TPB] = make_float2(p.x, p.y);
    }
#pragma unroll
    for (int i = 0; i < G2 / TPB; ++i)
        scnt[threadIdx.x + i * TPB] = 0u;
    __syncthreads();

#pragma unroll
    for (int i = 0; i < Nc / TPB; ++i) {
        float2 p = pts[threadIdx.x + i * TPB];
        atomicAdd(&scnt[cell_of(p.y) * G + cell_of(p.x)], 1u);
    }
    __syncthreads();

    // block exclusive scan of 4096 counters
    unsigned int v[16], sum = 0;
    const int base = threadIdx.x * 16;
#pragma unroll
    for (int i = 0; i < 16; ++i) { v[i] = scnt[base + i]; sum += v[i]; }
    part[threadIdx.x] = sum;
    __syncthreads();
    for (int off = 1; off < TPB; off <<= 1) {
        unsigned int a = (threadIdx.x >= off) ? part[threadIdx.x - off] : 0u;
        __syncthreads();
        if (threadIdx.x >= off) part[threadIdx.x] += a;
        __syncthreads();
    }
    unsigned int run = threadIdx.x ? part[threadIdx.x - 1] : 0u;
    unsigned short* st = g_start + sb * SST;
#pragma unroll
    for (int i = 0; i < 16; ++i) {
        scnt[base + i] = run;                       // scatter cursor
        st[base + i]   = (unsigned short)run;
        run += v[i];
    }
    if (threadIdx.x == TPB - 1) st[G2] = (unsigned short)run;   // 2048
    __syncthreads();

    float2* dst = g_sorted + (size_t)sb * Nc;
#pragma unroll
    for (int i = 0; i < Nc / TPB; ++i) {
        float2 p = pts[threadIdx.x + i * TPB];
        unsigned int pos = atomicAdd(&scnt[cell_of(p.y) * G + cell_of(p.x)], 1u);
        dst[pos] = p;
    }
}

// ---------------- Kernel 2: ring-search query ----------------
__global__ __launch_bounds__(TPB)
void query_kernel(const float* __restrict__ subcoef, float* __restrict__ out)
{
    __shared__ float2 tile[Nc];                  // db points (cell-sorted)
    __shared__ unsigned short sst[G2 + 1];       // db cell starts
    __shared__ float red[TPB / 32];

    int bid = blockIdx.x;
    const int chunk = bid & (QCH - 1);  bid >>= 3;
    const int b     = bid & (Bc - 1);   bid >>= 6;
    const int dir   = bid;                       // 0: preds->targs, 1: targs->preds
    const int qsb = dir * Bc + b;                // query set (set0 = preds)
    const int dsb = (1 - dir) * Bc + b;          // db set

    for (int t = threadIdx.x; t < Nc; t += TPB)  tile[t] = g_sorted[(size_t)dsb * Nc + t];
    for (int t = threadIdx.x; t <= G2; t += TPB) sst[t]  = g_start[dsb * SST + t];
    __syncthreads();

    // query = own set's sorted points (order-invariant loss; spatial sort
    // makes warp lanes cell-coherent)
    float2 q = g_sorted[(size_t)qsb * Nc + chunk * TPB + threadIdx.x];
    const float qx = q.x, qy = q.y;
    const int cx = cell_of(qx), cy = cell_of(qy);

    float best = CUDART_INF_F;                   // true squared distance
    float bx = 0.0f, by = 0.0f;

    // span scan: unroll-2 for MLP on the LDS chain
    auto scan = [&](int j, int je) {
        for (; j + 1 < je; j += 2) {
            float2 t0 = tile[j];
            float2 t1 = tile[j + 1];
            float dx0 = t0.x - qx, dy0 = t0.y - qy;
            float dx1 = t1.x - qx, dy1 = t1.y - qy;
            float s0 = fmaf(dx0, dx0, dy0 * dy0);
            float s1 = fmaf(dx1, dx1, dy1 * dy1);
            if (s0 < best) { best = s0; bx = t0.x; by = t0.y; }
            if (s1 < best) { best = s1; bx = t1.x; by = t1.y; }
        }
        if (j < je) {
            float2 t0 = tile[j];
            float dx0 = t0.x - qx, dy0 = t0.y - qy;
            float s0 = fmaf(dx0, dx0, dy0 * dy0);
            if (s0 < best) { best = s0; bx = t0.x; by = t0.y; }
        }
    };

    // fast path: unconditional 3x3 box (rings k=0,1): 3 contiguous row spans
    {
        const int xa = max(cx - 1, 0), xb = min(cx + 1, G - 1);
        const int ya = max(cy - 1, 0), yb = min(cy + 1, G - 1);
        for (int y = ya; y <= yb; ++y)
            scan(sst[y * G + xa], sst[y * G + xb + 1]);
    }

    // expansion: ring k; unscanned cells (Chebyshev >= k) have d >= (k-1)*CELL
    for (int k = 2; k < G; ++k) {
        float bd = (float)(k - 1) * CELL;
        if (best <= bd * bd) break;
        const int xa = max(cx - k, 0), xb = min(cx + k, G - 1);
        const int ya = max(cy - k, 0), yb = min(cy + k, G - 1);
        for (int y = ya; y <= yb; ++y) {
            if (y == cy - k || y == cy + k) {
                scan(sst[y * G + xa], sst[y * G + xb + 1]);
            } else {
                if (cx - k >= 0) {
                    int cc = y * G + cx - k;
                    scan(sst[cc], sst[cc + 1]);
                }
                if (cx + k < G) {
                    int cc = y * G + cx + k;
                    scan(sst[cc], sst[cc + 1]);
                }
            }
        }
    }

    const float cA = dir ? 1.0f : subcoef[0];
    const float cB = dir ? 1.0f : subcoef[1];
    float contrib = fabsf(qx - bx) * cA + fabsf(qy - by) * cB;

#pragma unroll
    for (int o = 16; o > 0; o >>= 1)
        contrib += __shfl_down_sync(0xffffffffu, contrib, o);
    if ((threadIdx.x & 31) == 0) red[threadIdx.x >> 5] = contrib;
    __syncthreads();
    if (threadIdx.x < 32) {
        float v = (threadIdx.x < TPB / 32) ? red[threadIdx.x] : 0.0f;
#pragma unroll
        for (int o = 4; o > 0; o >>= 1)
            v += __shfl_down_sync(0x000000ffu, v, o);
        if (threadIdx.x == 0) atomicAdd(out, v);
    }
}

extern "C" void kernel_launch(void* const* d_in, const int* in_sizes, int n_in,
                              void* d_out, int out_size)
{
    const float* preds   = (const float*)d_in[0];
    const float* targs   = (const float*)d_in[1];
    const float* subcoef = (const float*)d_in[2];
    float* out = (float*)d_out;

    bin_kernel  <<<NSB, TPB>>>(preds, targs, out);          // 128 blocks
    query_kernel<<<2 * Bc * QCH, TPB>>>(subcoef, out);      // 1024 blocks
}